// round 16
// baseline (speedup 1.0000x reference)
#include <cuda_runtime.h>
#include <cstdint>

#define NTHREADS 256

__device__ __forceinline__ float lrelu(float v) { return fmaxf(v, 0.01f * v); }

// pack two floats -> bf16x2 word (lo = first/even-k element, in low 16 bits)
__device__ __forceinline__ uint32_t pk(float lo, float hi) {
    uint32_t r;
    asm("cvt.rn.bf16x2.f32 %0, %1, %2;" : "=r"(r) : "f"(hi), "f"(lo));
    return r;
}
__device__ __forceinline__ float bf_lo(uint32_t wd) { return __uint_as_float(wd << 16); }
__device__ __forceinline__ float bf_hi(uint32_t wd) { return __uint_as_float(wd & 0xffff0000u); }

__device__ __forceinline__ void mma_bf16(float* d,
                                         uint32_t a0, uint32_t a1, uint32_t a2, uint32_t a3,
                                         uint32_t b0, uint32_t b1) {
    asm volatile("mma.sync.aligned.m16n8k16.row.col.f32.bf16.bf16.f32 "
                 "{%0,%1,%2,%3},{%4,%5,%6,%7},{%8,%9},{%0,%1,%2,%3};"
                 : "+f"(d[0]), "+f"(d[1]), "+f"(d[2]), "+f"(d[3])
                 : "r"(a0), "r"(a1), "r"(a2), "r"(a3), "r"(b0), "r"(b1));
}

// ---- shared memory layout (32-bit word offsets) ----
// region0 (reused over time):
#define OFF_XS    0        // 121 fp32 image (phase 1 only)
#define OFF_PP    128      // 8*88 = 704 packed im2col (phase 1 only)
#define OFF_W1S   832      // 64*12 = 768 packed conv1 weights -> 1600
#define OFF_A3    0        // 16*56 = 896 packed conv2 out
#define OFF_FLAT  1792     // 100 packed bf16x2 (flat 200)
#define OFF_FCS   1992     // 256 fp32 fc1 scratch
#define OFF_F1    2248     // 32 packed
#define OFF_F2    2312     // 32 fp32
#define OFF_F3    2344
#define OFF_F4    2360
#define OFF_FC2S  2368     // 128 fp32 -> 2496
// high region (packed bf16x2; strides bank-tiled):
#define OFF_A1    2880     // A1p [32 cp][88]  -> 5696
#define OFF_TH    5696     // THp [81 s][20]   -> 7316  (theta, i-pairs)
#define OFF_PH    7316     // PHp [16 ip][88]  -> 8724  (phi)
#define OFF_G     8724     // Gp  [48 tp][40]  -> 10644 (g, t-pairs; rows 40..47 zeroed)
#define OFF_Y     10644    // Yp  [16 ip][88]  -> 12052
#define OFF_RED   5696     // conv2 partials: 4 bufs x 1824 fp32 -> 12992 (TH..Y dead)
#define OFF_RED3  5696     // conv3 partials: 8 x 264 fp32
#define SMEM_FLOATS 12992
#define SMEM_BYTES  (SMEM_FLOATS * 4)

// ---- prepacked weights (device scratch, filled by prep kernel) ----
__device__ __align__(16) uint32_t g_w2fb[5 * 8 * 8 * 32];   // conv2 tap-pair frags
__device__ __align__(16) uint32_t g_w3fb[9 * 2 * 2 * 32];   // conv3 frags
__device__ __align__(16) uint32_t g_fw1Tp[100 * 64];        // fc1 packed [kp][j]
__device__ __align__(16) uint32_t g_fw2Tp[32 * 32];         // fc2 packed [kp][j]
__device__ __align__(16) uint32_t g_w96fb[6 * 4 * 4 * 32];  // phase-2 A frags (wt|wp|wg)
__device__ __align__(16) uint32_t g_wofb[4 * 2 * 4 * 32];   // phase-3c A frags (wo)

#define N_W2FB  (5 * 8 * 8 * 32)
#define N_W3FB  (9 * 2 * 2 * 32)
#define N_F1TP  (100 * 64)
#define N_F2TP  (32 * 32)
#define N_W96FB (6 * 4 * 4 * 32)
#define N_WOFB  (4 * 2 * 4 * 32)
#define PREP_TOTAL (N_W2FB + N_W3FB + N_F1TP + N_F2TP + N_W96FB + N_WOFB)

__global__ void prep_kernel(const float* __restrict__ w2, const float* __restrict__ w3,
                            const float* __restrict__ fw1, const float* __restrict__ fw2,
                            const float* __restrict__ wt, const float* __restrict__ wp,
                            const float* __restrict__ wg, const float* __restrict__ wo) {
    int i = blockIdx.x * blockDim.x + threadIdx.x;
    if (i < N_W2FB) {
        int lane = i & 31;
        int idx  = (i >> 5) & 7;
        int w    = (i >> 8) & 7;
        int tp   = i >> 11;                 // 0..4
        int g = lane >> 2, tg = lane & 3;
        int mt = idx >> 2, r = idx & 3;
        int o = mt * 16 + g + 8 * (r & 1);
        int tap = 2 * tp + (r >> 1);
        int c = w * 8 + 2 * tg;
        uint32_t v = 0;
        if (tap <= 8) {
            float lo = w2[o * 576 + c * 9 + tap];
            float hi = w2[o * 576 + (c + 1) * 9 + tap];
            v = pk(lo, hi);
        }
        g_w2fb[i] = v;
        return;
    }
    i -= N_W2FB;
    if (i < N_W3FB) {
        int lane = i & 31;
        int ridx = (i >> 5) & 1;
        int kc2  = (i >> 6) & 1;
        int t    = i >> 7;                  // 0..8
        int g = lane >> 2, tg = lane & 3;
        int o = g;                          // output channel 0..7
        int c = kc2 * 16 + 8 * ridx + 2 * tg;
        g_w3fb[i] = pk(w3[o * 288 + c * 9 + t], w3[o * 288 + (c + 1) * 9 + t]);
        return;
    }
    i -= N_W3FB;
    if (i < N_F1TP) {
        int kp = i / 64, jj = i % 64;
        g_fw1Tp[i] = pk(fw1[jj * 200 + 2 * kp], fw1[jj * 200 + 2 * kp + 1]);
        return;
    }
    i -= N_F1TP;
    if (i < N_F2TP) {
        int kp = i / 32, jj = i % 32;
        g_fw2Tp[i] = pk(fw2[jj * 64 + 2 * kp], fw2[jj * 64 + 2 * kp + 1]);
        return;
    }
    i -= N_F2TP;
    if (i < N_W96FB) {
        int lane = i & 31;
        int r    = (i >> 5) & 3;
        int kc   = (i >> 7) & 3;
        int wm   = i >> 9;                  // 0..5
        int g = lane >> 2, tg = lane & 3;
        int row = wm * 16 + g + 8 * (r & 1);    // 0..95
        int k0  = kc * 16 + 8 * (r >> 1) + 2 * tg;
        const float* src = (row < 32) ? wt : ((row < 64) ? wp : wg);
        g_w96fb[i] = pk(src[(row & 31) * 64 + k0], src[(row & 31) * 64 + k0 + 1]);
        return;
    }
    i -= N_W96FB;
    if (i < N_WOFB) {
        int lane = i & 31;
        int r    = (i >> 5) & 3;
        int kc2  = (i >> 7) & 1;
        int mt   = i >> 8;                  // 0..3
        int g = lane >> 2, tg = lane & 3;
        int row = mt * 16 + g + 8 * (r & 1);    // 0..63
        int k0  = kc2 * 16 + 8 * (r >> 1) + 2 * tg;
        g_wofb[i] = pk(wo[row * 32 + k0], wo[row * 32 + k0 + 1]);
    }
}

__global__ void __launch_bounds__(NTHREADS, 3) braggnn_kernel(
    const float* __restrict__ x,
    const float* __restrict__ w1, const float* __restrict__ b1,
    const float* __restrict__ bt, const float* __restrict__ bp,
    const float* __restrict__ bg, const float* __restrict__ bo,
    const float* __restrict__ b2, const float* __restrict__ b3,
    const float* __restrict__ fb1, const float* __restrict__ fb2,
    const float* __restrict__ fw3, const float* __restrict__ fb3,
    const float* __restrict__ fw4, const float* __restrict__ fb4,
    const float* __restrict__ fwo, const float* __restrict__ fbo,
    float* __restrict__ out)
{
    extern __shared__ float sm[];
    uint32_t* smu = (uint32_t*)sm;
    const int b    = blockIdx.x;
    const int tid  = threadIdx.x;
    const int w    = tid >> 5;
    const int lane = tid & 31;
    const int g    = lane >> 2;
    const int tg   = lane & 3;

    // ---- init: image, conv1 weights (packed), Gp pad rows ----
    for (int i = tid; i < 121; i += NTHREADS) sm[OFF_XS + i] = x[b * 121 + i];
    for (int i = tid; i < 512; i += NTHREADS) {        // W1Sp [64][12], 8 words used/row
        int o = i >> 3, ip = i & 7;
        float lo = (2 * ip <= 8) ? w1[o * 9 + 2 * ip] : 0.f;
        float hi = (2 * ip + 1 <= 8) ? w1[o * 9 + 2 * ip + 1] : 0.f;
        smu[OFF_W1S + o * 12 + ip] = pk(lo, hi);
    }
    for (int i = tid; i < 320; i += NTHREADS) smu[OFF_G + 40 * 40 + i] = 0u;  // Gp rows 40..47
    __syncthreads();

    // ---- im2col packed Pp [8 kp][88] ----
    for (int i = tid; i < 704; i += NTHREADS) {
        int kp = i / 88, s = i - kp * 88;
        float lo = 0.f, hi = 0.f;
        if (s < 81) {
            int t0 = 2 * kp, t1 = 2 * kp + 1;
            if (t0 <= 8) lo = sm[OFF_XS + (s / 9 + t0 / 3) * 11 + (s % 9) + t0 % 3];
            if (t1 <= 8) hi = sm[OFF_XS + (s / 9 + t1 / 3) * 11 + (s % 9) + t1 % 3];
        }
        smu[OFF_PP + kp * 88 + s] = pk(lo, hi);
    }
    __syncthreads();

    // ---- phase 1 (mma): A1[64][81] = W1[64][16] @ P[16][81], store packed pairs ----
    {
        const int m0 = (w >> 1) * 16;
        const int nbeg = (w & 1) ? 6 : 0, nend = (w & 1) ? 11 : 6;
        float D[6][4];
        #pragma unroll
        for (int j = 0; j < 6; j++) { D[j][0]=0.f; D[j][1]=0.f; D[j][2]=0.f; D[j][3]=0.f; }
        uint32_t a0 = smu[OFF_W1S + (m0 + g)     * 12 + tg];
        uint32_t a1 = smu[OFF_W1S + (m0 + g + 8) * 12 + tg];
        uint32_t a2 = smu[OFF_W1S + (m0 + g)     * 12 + tg + 4];
        uint32_t a3 = smu[OFF_W1S + (m0 + g + 8) * 12 + tg + 4];
        {
            int j = 0;
            for (int nt = nbeg; nt < nend; nt++, j++) {
                uint32_t b0 = smu[OFF_PP + tg       * 88 + nt * 8 + g];
                uint32_t b1 = smu[OFF_PP + (tg + 4) * 88 + nt * 8 + g];
                mma_bf16(D[j], a0, a1, a2, a3, b0, b1);
            }
        }
        const int c0 = m0 + g, c1 = m0 + g + 8;
        const float bia0 = b1[c0], bia1 = b1[c1];
        int j = 0;
        for (int nt = nbeg; nt < nend; nt++, j++)
            #pragma unroll
            for (int dd = 0; dd < 2; dd++) {
                int s = nt * 8 + 2 * tg + dd;
                float v0 = D[j][dd]     + bia0;
                float v1 = D[j][2 + dd] + bia1;
                float p0 = __shfl_xor_sync(0xffffffffu, v0, 4);
                float p1 = __shfl_xor_sync(0xffffffffu, v1, 4);
                if (!(g & 1) && s < 81) {
                    smu[OFF_A1 + (c0 >> 1) * 88 + s] = pk(v0, p0);
                    smu[OFF_A1 + (c1 >> 1) * 88 + s] = pk(v1, p1);
                }
            }
    }
    __syncthreads();

    // ---- phase 2 (mma): [theta|phi|g][96][81] = W96 @ A1, 8-warp split ----
    // warps 0..5: m-tile w, nt 0..7 ; warps 6..7: three m-tiles' nt 8..10 tails
    if (w < 6) {
        float D[8][4];
        #pragma unroll
        for (int nt = 0; nt < 8; nt++) { D[nt][0]=0.f; D[nt][1]=0.f; D[nt][2]=0.f; D[nt][3]=0.f; }
        for (int kc = 0; kc < 4; kc++) {
            const uint32_t* af = &g_w96fb[(w * 4 + kc) * 128];
            uint32_t a0 = af[lane], a1 = af[32 + lane], a2 = af[64 + lane], a3 = af[96 + lane];
            #pragma unroll
            for (int nt = 0; nt < 8; nt++) {
                uint32_t b0 = smu[OFF_A1 + (kc * 8 + tg)     * 88 + nt * 8 + g];
                uint32_t b1 = smu[OFF_A1 + (kc * 8 + tg + 4) * 88 + nt * 8 + g];
                mma_bf16(D[nt], a0, a1, a2, a3, b0, b1);
            }
        }
        const int mat = w >> 1;                          // 0=theta 1=phi 2=g
        const float* bias = (mat == 0) ? bt : ((mat == 1) ? bp : bg);
        const int ch0 = (w & 1) * 16 + g, ch1 = ch0 + 8;
        const float bv0 = bias[ch0], bv1 = bias[ch1];
        if (mat == 2) {
            // Gp [tp][i]: t-pairs are local (dd); nt<8 -> s0<=62, both pair elems valid
            #pragma unroll
            for (int nt = 0; nt < 8; nt++) {
                float v00 = D[nt][0] + bv0, v01 = D[nt][1] + bv0;
                float v10 = D[nt][2] + bv1, v11 = D[nt][3] + bv1;
                smu[OFF_G + (nt * 4 + tg) * 40 + ch0] = pk(v00, v01);
                smu[OFF_G + (nt * 4 + tg) * 40 + ch1] = pk(v10, v11);
            }
        } else {
            // THp [s][ip] / PHp [ip][t]: i-pairs via g-parity shfl; nt<8 -> s<=63
            #pragma unroll
            for (int nt = 0; nt < 8; nt++)
                #pragma unroll
                for (int dd = 0; dd < 2; dd++) {
                    int s = nt * 8 + 2 * tg + dd;
                    float v0 = D[nt][dd]     + bv0;
                    float v1 = D[nt][2 + dd] + bv1;
                    float p0 = __shfl_xor_sync(0xffffffffu, v0, 4);
                    float p1 = __shfl_xor_sync(0xffffffffu, v1, 4);
                    if (!(g & 1)) {
                        if (mat == 0) {
                            smu[OFF_TH + s * 20 + (ch0 >> 1)] = pk(v0, p0);
                            smu[OFF_TH + s * 20 + (ch1 >> 1)] = pk(v1, p1);
                        } else {
                            smu[OFF_PH + (ch0 >> 1) * 88 + s] = pk(v0, p0);
                            smu[OFF_PH + (ch1 >> 1) * 88 + s] = pk(v1, p1);
                        }
                    }
                }
        }
    } else {
        // warps 6,7: tiles tbase..tbase+2, nt 8..10 (B frags shared across tiles)
        const int tbase = (w - 6) * 3;
        float D[3][3][4];
        #pragma unroll
        for (int tl = 0; tl < 3; tl++)
            #pragma unroll
            for (int nl = 0; nl < 3; nl++) { D[tl][nl][0]=0.f; D[tl][nl][1]=0.f; D[tl][nl][2]=0.f; D[tl][nl][3]=0.f; }
        for (int kc = 0; kc < 4; kc++) {
            uint32_t bb[3][2];
            #pragma unroll
            for (int nl = 0; nl < 3; nl++) {
                int nt = 8 + nl;
                bb[nl][0] = smu[OFF_A1 + (kc * 8 + tg)     * 88 + nt * 8 + g];
                bb[nl][1] = smu[OFF_A1 + (kc * 8 + tg + 4) * 88 + nt * 8 + g];
            }
            #pragma unroll
            for (int tl = 0; tl < 3; tl++) {
                const uint32_t* af = &g_w96fb[((tbase + tl) * 4 + kc) * 128];
                uint32_t a0 = af[lane], a1 = af[32 + lane], a2 = af[64 + lane], a3 = af[96 + lane];
                #pragma unroll
                for (int nl = 0; nl < 3; nl++)
                    mma_bf16(D[tl][nl], a0, a1, a2, a3, bb[nl][0], bb[nl][1]);
            }
        }
        #pragma unroll
        for (int tl = 0; tl < 3; tl++) {
            const int wm = tbase + tl;
            const int mat = wm >> 1;
            const float* bias = (mat == 0) ? bt : ((mat == 1) ? bp : bg);
            const int ch0 = (wm & 1) * 16 + g, ch1 = ch0 + 8;
            const float bv0 = bias[ch0], bv1 = bias[ch1];
            #pragma unroll
            for (int nl = 0; nl < 3; nl++) {
                const int nt = 8 + nl;
                if (mat == 2) {
                    int s0 = nt * 8 + 2 * tg;
                    if (s0 < 81) {
                        float v00 = D[tl][nl][0] + bv0, v01 = D[tl][nl][1] + bv0;
                        float v10 = D[tl][nl][2] + bv1, v11 = D[tl][nl][3] + bv1;
                        float h0 = (s0 + 1 < 81) ? v01 : 0.f;
                        float h1 = (s0 + 1 < 81) ? v11 : 0.f;
                        smu[OFF_G + (nt * 4 + tg) * 40 + ch0] = pk(v00, h0);
                        smu[OFF_G + (nt * 4 + tg) * 40 + ch1] = pk(v10, h1);
                    }
                } else {
                    #pragma unroll
                    for (int dd = 0; dd < 2; dd++) {
                        int s = nt * 8 + 2 * tg + dd;
                        float v0 = D[tl][nl][dd]     + bv0;
                        float v1 = D[tl][nl][2 + dd] + bv1;
                        float p0 = __shfl_xor_sync(0xffffffffu, v0, 4);
                        float p1 = __shfl_xor_sync(0xffffffffu, v1, 4);
                        if (!(g & 1) && s < 81) {
                            if (mat == 0) {
                                smu[OFF_TH + s * 20 + (ch0 >> 1)] = pk(v0, p0);
                                smu[OFF_TH + s * 20 + (ch1 >> 1)] = pk(v1, p1);
                            } else {
                                smu[OFF_PH + (ch0 >> 1) * 88 + s] = pk(v0, p0);
                                smu[OFF_PH + (ch1 >> 1) * 88 + s] = pk(v1, p1);
                            }
                        }
                    }
                }
            }
        }
    }
    __syncthreads();

    // ---- phase 3a+3b fused: logits -> register softmax -> (local repack) -> Y ----
    if (w < 6) {
        const int m0 = w * 16;
        const int r0 = min(m0 + g, 80), r1 = min(m0 + g + 8, 80);
        float D[11][4];
        #pragma unroll
        for (int nt = 0; nt < 11; nt++) { D[nt][0]=0.f; D[nt][1]=0.f; D[nt][2]=0.f; D[nt][3]=0.f; }
        #pragma unroll
        for (int kc2 = 0; kc2 < 2; kc2++) {
            uint32_t a0 = smu[OFF_TH + r0 * 20 + kc2 * 8 + tg];
            uint32_t a1 = smu[OFF_TH + r1 * 20 + kc2 * 8 + tg];
            uint32_t a2 = smu[OFF_TH + r0 * 20 + kc2 * 8 + tg + 4];
            uint32_t a3 = smu[OFF_TH + r1 * 20 + kc2 * 8 + tg + 4];
            #pragma unroll
            for (int nt = 0; nt < 11; nt++) {
                uint32_t b0 = smu[OFF_PH + (kc2 * 8 + tg)     * 88 + nt * 8 + g];
                uint32_t b1 = smu[OFF_PH + (kc2 * 8 + tg + 4) * 88 + nt * 8 + g];
                mma_bf16(D[nt], a0, a1, a2, a3, b0, b1);
            }
        }
        // register softmax (rows m0+g, m0+g+8)
        float mx0 = -1e30f, mx1 = -1e30f;
        #pragma unroll
        for (int nt = 0; nt < 11; nt++)
            #pragma unroll
            for (int dd = 0; dd < 2; dd++) {
                int t = nt * 8 + 2 * tg + dd;
                if (t < 81) { mx0 = fmaxf(mx0, D[nt][dd]); mx1 = fmaxf(mx1, D[nt][2 + dd]); }
            }
        mx0 = fmaxf(mx0, __shfl_xor_sync(0xffffffffu, mx0, 1));
        mx0 = fmaxf(mx0, __shfl_xor_sync(0xffffffffu, mx0, 2));
        mx1 = fmaxf(mx1, __shfl_xor_sync(0xffffffffu, mx1, 1));
        mx1 = fmaxf(mx1, __shfl_xor_sync(0xffffffffu, mx1, 2));
        float s0 = 0.f, s1 = 0.f;
        #pragma unroll
        for (int nt = 0; nt < 11; nt++)
            #pragma unroll
            for (int dd = 0; dd < 2; dd++) {
                int t = nt * 8 + 2 * tg + dd;
                float e0 = (t < 81) ? __expf(D[nt][dd]     - mx0) : 0.f;
                float e1 = (t < 81) ? __expf(D[nt][2 + dd] - mx1) : 0.f;
                D[nt][dd] = e0; D[nt][2 + dd] = e1;
                s0 += e0; s1 += e1;
            }
        s0 += __shfl_xor_sync(0xffffffffu, s0, 1);
        s0 += __shfl_xor_sync(0xffffffffu, s0, 2);
        s1 += __shfl_xor_sync(0xffffffffu, s1, 1);
        s1 += __shfl_xor_sync(0xffffffffu, s1, 2);
        const float inv0 = 1.0f / s0, inv1 = 1.0f / s1;
        #pragma unroll
        for (int nt = 0; nt < 11; nt++)
            #pragma unroll
            for (int dd = 0; dd < 2; dd++) {
                D[nt][dd]     *= inv0;
                D[nt][2 + dd] *= inv1;
            }
        // 3b: Y = attn @ G; A-frags are register-local packs of D
        float Y[4][4];
        #pragma unroll
        for (int nt = 0; nt < 4; nt++) { Y[nt][0]=0.f; Y[nt][1]=0.f; Y[nt][2]=0.f; Y[nt][3]=0.f; }
        #pragma unroll
        for (int kc = 0; kc < 6; kc++) {
            uint32_t a0, a1, a2, a3;
            if (kc < 5) {
                a0 = pk(D[2 * kc][0],     D[2 * kc][1]);
                a1 = pk(D[2 * kc][2],     D[2 * kc][3]);
                a2 = pk(D[2 * kc + 1][0], D[2 * kc + 1][1]);
                a3 = pk(D[2 * kc + 1][2], D[2 * kc + 1][3]);
            } else {
                a0 = pk(D[10][0], D[10][1]);
                a1 = pk(D[10][2], D[10][3]);
                a2 = 0u; a3 = 0u;
            }
            #pragma unroll
            for (int nt = 0; nt < 4; nt++) {
                uint32_t b0 = smu[OFF_G + (kc * 8 + tg)     * 40 + nt * 8 + g];
                uint32_t b1 = smu[OFF_G + (kc * 8 + tg + 4) * 40 + nt * 8 + g];
                mma_bf16(Y[nt], a0, a1, a2, a3, b0, b1);
            }
        }
        const int sr0 = m0 + g, sr1 = m0 + g + 8;
        #pragma unroll
        for (int nt = 0; nt < 4; nt++) {
            if (sr0 < 81) smu[OFF_Y + (nt * 4 + tg) * 88 + sr0] = pk(Y[nt][0], Y[nt][1]);
            if (sr1 < 81) smu[OFF_Y + (nt * 4 + tg) * 88 + sr1] = pk(Y[nt][2], Y[nt][3]);
        }
    }
    __syncthreads();

    // ---- phase 3c (mma): Z[64][81] = wo @ Y^T + bo + residual, lrelu -> A1p ----
    {
        const int mt = w >> 1;
        const int nbeg = (w & 1) ? 6 : 0, nend = (w & 1) ? 11 : 6;
        float D[6][4];
        #pragma unroll
        for (int j = 0; j < 6; j++) { D[j][0]=0.f; D[j][1]=0.f; D[j][2]=0.f; D[j][3]=0.f; }
        #pragma unroll
        for (int kc2 = 0; kc2 < 2; kc2++) {
            const uint32_t* af = &g_wofb[(mt * 2 + kc2) * 128];
            uint32_t a0 = af[lane], a1 = af[32 + lane], a2 = af[64 + lane], a3 = af[96 + lane];
            int j = 0;
            for (int nt = nbeg; nt < nend; nt++, j++) {
                uint32_t b0 = smu[OFF_Y + (kc2 * 8 + tg)     * 88 + nt * 8 + g];
                uint32_t b1 = smu[OFF_Y + (kc2 * 8 + tg + 4) * 88 + nt * 8 + g];
                mma_bf16(D[j], a0, a1, a2, a3, b0, b1);
            }
        }
        const int c0 = mt * 16 + g, c1 = c0 + 8;
        const float bo0 = bo[c0], bo1 = bo[c1];
        int j = 0;
        for (int nt = nbeg; nt < nend; nt++, j++)
            #pragma unroll
            for (int dd = 0; dd < 2; dd++) {
                int s = nt * 8 + 2 * tg + dd;
                uint32_t w0 = smu[OFF_A1 + (c0 >> 1) * 88 + s];
                uint32_t w1v = smu[OFF_A1 + (c1 >> 1) * 88 + s];
                float r0v = (g & 1) ? bf_hi(w0)  : bf_lo(w0);
                float r1v = (g & 1) ? bf_hi(w1v) : bf_lo(w1v);
                float v0 = lrelu(D[j][dd]     + bo0 + r0v);
                float v1 = lrelu(D[j][2 + dd] + bo1 + r1v);
                float p0 = __shfl_xor_sync(0xffffffffu, v0, 4);
                float p1 = __shfl_xor_sync(0xffffffffu, v1, 4);
                if (!(g & 1) && s < 81) {
                    smu[OFF_A1 + (c0 >> 1) * 88 + s] = pk(v0, p0);
                    smu[OFF_A1 + (c1 >> 1) * 88 + s] = pk(v1, p1);
                }
            }
    }
    __syncthreads();

    // ---- phase 4 (mma): conv2 via tap-pair K=16 GEMMs, K-split by channel ----
    {
        const int c0p = w * 4;          // A1p row base (channel pairs)
        float* buf = &sm[OFF_RED + (w & 3) * 1824];
        #pragma unroll
        for (int pass = 0; pass < 2; pass++) {
            const int ntb = pass ? 4 : 0;
            const int ntn = pass ? 3 : 4;
            int rmv[4];
            #pragma unroll
            for (int q = 0; q < 4; q++) {
                int qq = (q < ntn) ? q : (ntn - 1);
                int p = (ntb + qq) * 8 + g;
                rmv[q] = (p < 49) ? (p / 7) * 9 + (p % 7) : 0;
            }
            float D[8][4];
            #pragma unroll
            for (int j = 0; j < 8; j++) { D[j][0]=0.f; D[j][1]=0.f; D[j][2]=0.f; D[j][3]=0.f; }
            for (int tp = 0; tp < 5; tp++) {
                int ta = 2 * tp, tb = (2 * tp + 1 <= 8) ? 2 * tp + 1 : 8;
                int off0 = (ta / 3) * 9 + ta % 3;
                int off1 = (tb / 3) * 9 + tb % 3;
                const uint32_t* af = &g_w2fb[(tp * 8 + w) * 256];
                uint32_t A[8];
                #pragma unroll
                for (int r = 0; r < 8; r++) A[r] = af[r * 32 + lane];
                for (int q = 0; q < ntn; q++) {
                    uint32_t b0 = smu[OFF_A1 + (c0p + tg) * 88 + rmv[q] + off0];
                    uint32_t b1 = smu[OFF_A1 + (c0p + tg) * 88 + rmv[q] + off1];
                    mma_bf16(D[q],     A[0], A[1], A[2], A[3], b0, b1);
                    mma_bf16(D[4 + q], A[4], A[5], A[6], A[7], b0, b1);
                }
            }
            if (w < 4) {
                for (int mt = 0; mt < 2; mt++)
                    for (int q = 0; q < ntn; q++)
                        #pragma unroll
                        for (int dd = 0; dd < 2; dd++) {
                            int o0 = mt * 16 + g, p = (ntb + q) * 8 + 2 * tg + dd;
                            buf[o0 * 57 + p]       = D[mt * 4 + q][dd];
                            buf[(o0 + 8) * 57 + p] = D[mt * 4 + q][2 + dd];
                        }
            }
            __syncthreads();
            if (w >= 4) {
                for (int mt = 0; mt < 2; mt++)
                    for (int q = 0; q < ntn; q++)
                        #pragma unroll
                        for (int dd = 0; dd < 2; dd++) {
                            int o0 = mt * 16 + g, p = (ntb + q) * 8 + 2 * tg + dd;
                            buf[o0 * 57 + p]       += D[mt * 4 + q][dd];
                            buf[(o0 + 8) * 57 + p] += D[mt * 4 + q][2 + dd];
                        }
            }
        }
        __syncthreads();
    }
    for (int e = tid; e < 784; e += NTHREADS) {     // reduce + bias + lrelu -> A3p packed
        int op = e / 49, p = e - op * 49;
        float s0 = b2[2 * op], s1 = b2[2 * op + 1];
        #pragma unroll
        for (int k = 0; k < 4; k++) {
            s0 += sm[OFF_RED + k * 1824 + (2 * op)     * 57 + p];
            s1 += sm[OFF_RED + k * 1824 + (2 * op + 1) * 57 + p];
        }
        smu[OFF_A3 + op * 56 + p] = pk(lrelu(s0), lrelu(s1));
    }
    __syncthreads();

    // ---- phase 5 (mma): conv3, taps split across warps ----
    {
        int rmv[4];
        #pragma unroll
        for (int nt = 0; nt < 4; nt++) {
            int n = nt * 8 + g;
            rmv[nt] = (n < 25) ? (n / 5) * 7 + (n % 5) : 0;
        }
        float D[4][4];
        #pragma unroll
        for (int nt = 0; nt < 4; nt++) { D[nt][0]=0.f; D[nt][1]=0.f; D[nt][2]=0.f; D[nt][3]=0.f; }
        for (int t = w; t < 9; t += 8) {
            const int off = (t / 3) * 7 + (t % 3);
            #pragma unroll
            for (int kc2 = 0; kc2 < 2; kc2++) {
                uint32_t a0 = g_w3fb[((t * 2 + kc2) * 2 + 0) * 32 + lane];
                uint32_t a2 = g_w3fb[((t * 2 + kc2) * 2 + 1) * 32 + lane];
                #pragma unroll
                for (int nt = 0; nt < 4; nt++) {
                    uint32_t b0 = smu[OFF_A3 + (kc2 * 8 + tg)     * 56 + rmv[nt] + off];
                    uint32_t b1 = smu[OFF_A3 + (kc2 * 8 + tg + 4) * 56 + rmv[nt] + off];
                    mma_bf16(D[nt], a0, 0u, a2, 0u, b0, b1);
                }
            }
        }
        float* buf3 = &sm[OFF_RED3 + w * 264];
        #pragma unroll
        for (int nt = 0; nt < 4; nt++)
            #pragma unroll
            for (int dd = 0; dd < 2; dd++)
                buf3[g * 33 + nt * 8 + 2 * tg + dd] = D[nt][dd];
    }
    __syncthreads();
    if (tid < 100) {     // reduce 8 tap-partials + bias + lrelu -> flat packed
        int f0 = 2 * tid, f1 = f0 + 1;
        int o0 = f0 / 25, p0 = f0 % 25;
        int o1 = f1 / 25, p1 = f1 % 25;
        float sA = b3[o0], sB = b3[o1];
        #pragma unroll
        for (int ww = 0; ww < 8; ww++) {
            sA += sm[OFF_RED3 + ww * 264 + o0 * 33 + p0];
            sB += sm[OFF_RED3 + ww * 264 + o1 * 33 + p1];
        }
        smu[OFF_FLAT + tid] = pk(lrelu(sA), lrelu(sB));
    }
    __syncthreads();

    // ---- phase 6: MLP (fc1/fc2 bf16-packed, rest fp32) ----
    float* scr  = &sm[OFF_FCS];
    float* sc2  = &sm[OFF_FC2S];
    float* f2 = &sm[OFF_F2];
    float* f3 = &sm[OFF_F3];
    float* f4 = &sm[OFF_F4];

    {   // fc1: 200 -> 64, packed k-pairs
        int q = tid >> 6, j = tid & 63;
        float acc = 0.f;
        int k0 = q * 25;
        for (int kp = 0; kp < 25; kp++) {
            uint32_t wv = g_fw1Tp[(k0 + kp) * 64 + j];
            uint32_t xv = smu[OFF_FLAT + k0 + kp];
            acc += bf_lo(wv) * bf_lo(xv) + bf_hi(wv) * bf_hi(xv);
        }
        scr[q * 64 + j] = acc;
    }
    __syncthreads();
    if (tid < 32) {     // reduce + lrelu + pack f1
        int j0 = 2 * tid, j1 = j0 + 1;
        float a0 = scr[j0] + scr[64 + j0] + scr[128 + j0] + scr[192 + j0] + fb1[j0];
        float a1 = scr[j1] + scr[64 + j1] + scr[128 + j1] + scr[192 + j1] + fb1[j1];
        smu[OFF_F1 + tid] = pk(lrelu(a0), lrelu(a1));
    }
    __syncthreads();
    if (tid < 128) {    // fc2: 64 -> 32, packed k-pairs
        int q = tid >> 5, j = tid & 31;
        float acc = 0.f;
        int k0 = q * 8;
        for (int kp = 0; kp < 8; kp++) {
            uint32_t wv = g_fw2Tp[(k0 + kp) * 32 + j];
            uint32_t xv = smu[OFF_F1 + k0 + kp];
            acc += bf_lo(wv) * bf_lo(xv) + bf_hi(wv) * bf_hi(xv);
        }
        sc2[q * 32 + j] = acc;
    }
    __syncthreads();
    if (tid < 32)
        f2[tid] = lrelu(sc2[tid] + sc2[32 + tid] + sc2[64 + tid] + sc2[96 + tid] + fb2[tid]);
    __syncthreads();
    if (tid < 64) {     // fc3: 32 -> 16
        int j = tid >> 2, q = tid & 3;
        float acc = 0.f;
        const float* wr = &fw3[j * 32 + q * 8];
        for (int k = 0; k < 8; k++) acc += wr[k] * f2[q * 8 + k];
        acc += __shfl_xor_sync(0xffffffffu, acc, 1);
        acc += __shfl_xor_sync(0xffffffffu, acc, 2);
        if (q == 0) f3[j] = lrelu(acc + fb3[j]);
    }
    __syncthreads();
    if (tid < 32) {     // fc4: 16 -> 8
        int j = tid >> 2, q = tid & 3;
        float acc = 0.f;
        const float* wr = &fw4[j * 16 + q * 4];
        for (int k = 0; k < 4; k++) acc += wr[k] * f3[q * 4 + k];
        acc += __shfl_xor_sync(0xffffffffu, acc, 1);
        acc += __shfl_xor_sync(0xffffffffu, acc, 2);
        if (q == 0) f4[j] = lrelu(acc + fb4[j]);
    }
    __syncthreads();
    if (tid < 2) {      // fco: 8 -> 2
        float acc = fbo[tid];
        const float* wr = &fwo[tid * 8];
        #pragma unroll
        for (int k = 0; k < 8; k++) acc += wr[k] * f4[k];
        out[b * 2 + tid] = acc;
    }
}

extern "C" void kernel_launch(void* const* d_in, const int* in_sizes, int n_in,
                              void* d_out, int out_size) {
    const float* x   = (const float*)d_in[0];
    const float* w1  = (const float*)d_in[1];
    const float* b1  = (const float*)d_in[2];
    const float* wt  = (const float*)d_in[3];
    const float* bt  = (const float*)d_in[4];
    const float* wp  = (const float*)d_in[5];
    const float* bp  = (const float*)d_in[6];
    const float* wg  = (const float*)d_in[7];
    const float* bg  = (const float*)d_in[8];
    const float* wo  = (const float*)d_in[9];
    const float* bo  = (const float*)d_in[10];
    const float* w2  = (const float*)d_in[11];
    const float* b2  = (const float*)d_in[12];
    const float* w3  = (const float*)d_in[13];
    const float* b3  = (const float*)d_in[14];
    const float* fw1 = (const float*)d_in[15];
    const float* fb1 = (const float*)d_in[16];
    const float* fw2 = (const float*)d_in[17];
    const float* fb2 = (const float*)d_in[18];
    const float* fw3 = (const float*)d_in[19];
    const float* fb3 = (const float*)d_in[20];
    const float* fw4 = (const float*)d_in[21];
    const float* fb4 = (const float*)d_in[22];
    const float* fwo = (const float*)d_in[23];
    const float* fbo = (const float*)d_in[24];
    float* out = (float*)d_out;

    int B = in_sizes[0] / 121;

    prep_kernel<<<(PREP_TOTAL + 255) / 256, 256>>>(w2, w3, fw1, fw2, wt, wp, wg, wo);

    cudaFuncSetAttribute(braggnn_kernel,
                         cudaFuncAttributeMaxDynamicSharedMemorySize, SMEM_BYTES);
    braggnn_kernel<<<B, NTHREADS, SMEM_BYTES>>>(
        x, w1, b1, bt, bp, bg, bo, b2, b3,
        fb1, fb2, fw3, fb3, fw4, fb4, fwo, fbo, out);
}

// round 17
// speedup vs baseline: 1.0055x; 1.0055x over previous
#include <cuda_runtime.h>
#include <cstdint>

#define NTHREADS 256

__device__ __forceinline__ float lrelu(float v) { return fmaxf(v, 0.01f * v); }

// pack two floats -> bf16x2 word (lo = first/even-k element, in low 16 bits)
__device__ __forceinline__ uint32_t pk(float lo, float hi) {
    uint32_t r;
    asm("cvt.rn.bf16x2.f32 %0, %1, %2;" : "=r"(r) : "f"(hi), "f"(lo));
    return r;
}
__device__ __forceinline__ float bf_lo(uint32_t wd) { return __uint_as_float(wd << 16); }
__device__ __forceinline__ float bf_hi(uint32_t wd) { return __uint_as_float(wd & 0xffff0000u); }

__device__ __forceinline__ void mma_bf16(float* d,
                                         uint32_t a0, uint32_t a1, uint32_t a2, uint32_t a3,
                                         uint32_t b0, uint32_t b1) {
    asm volatile("mma.sync.aligned.m16n8k16.row.col.f32.bf16.bf16.f32 "
                 "{%0,%1,%2,%3},{%4,%5,%6,%7},{%8,%9},{%0,%1,%2,%3};"
                 : "+f"(d[0]), "+f"(d[1]), "+f"(d[2]), "+f"(d[3])
                 : "r"(a0), "r"(a1), "r"(a2), "r"(a3), "r"(b0), "r"(b1));
}

// ---- shared memory layout (32-bit word offsets) ----
// region0 (reused over time):
#define OFF_XS    0        // 121 fp32 image (phase 1 only)
#define OFF_PP    128      // 8*88 = 704 packed im2col (phase 1 only)
#define OFF_W1S   832      // 64*12 = 768 packed conv1 weights -> 1600
#define OFF_A3    0        // 16*56 = 896 packed conv2 out
#define OFF_FLAT  1792     // 100 packed bf16x2 (flat 200)
#define OFF_FCS   1992     // 256 fp32 fc1 scratch
#define OFF_F1    2248     // 32 packed
#define OFF_F2    2312     // 32 fp32
#define OFF_F3    2344
#define OFF_F4    2360
#define OFF_FC2S  2368     // 128 fp32 -> 2496
// high region (packed bf16x2; strides bank-tiled):
#define OFF_A1    2880     // A1p [32 cp][88]  -> 5696
#define OFF_TH    5696     // THp [81 s][20]   -> 7316  (theta, i-pairs)
#define OFF_PH    7316     // PHp [16 ip][88]  -> 8724  (phi)
#define OFF_G     8724     // Gp  [48 tp][40]  -> 10644 (g, t-pairs; rows 40..47 zeroed)
#define OFF_Y     10644    // Yp  [16 ip][88]  -> 12052
#define OFF_RED   5696     // conv2 partials: 4 bufs x 1824 fp32 -> 12992 (TH..Y dead)
#define OFF_RED3  5696     // conv3 partials: 8 x 264 fp32
#define SMEM_FLOATS 12992
#define SMEM_BYTES  (SMEM_FLOATS * 4)

// ---- prepacked weights (device scratch, filled by prep kernel) ----
__device__ __align__(16) uint32_t g_w2fb[5 * 8 * 8 * 32];   // conv2 tap-pair frags
__device__ __align__(16) uint32_t g_w3fb[9 * 2 * 2 * 32];   // conv3 frags
__device__ __align__(16) uint32_t g_fw1Tp[100 * 64];        // fc1 packed [kp][j]
__device__ __align__(16) uint32_t g_fw2Tp[32 * 32];         // fc2 packed [kp][j]
__device__ __align__(16) uint32_t g_w96fb[6 * 4 * 4 * 32];  // phase-2 A frags (wt|wp|wg)
__device__ __align__(16) uint32_t g_wofb[4 * 2 * 4 * 32];   // phase-3c A frags (wo)

#define N_W2FB  (5 * 8 * 8 * 32)
#define N_W3FB  (9 * 2 * 2 * 32)
#define N_F1TP  (100 * 64)
#define N_F2TP  (32 * 32)
#define N_W96FB (6 * 4 * 4 * 32)
#define N_WOFB  (4 * 2 * 4 * 32)
#define PREP_TOTAL (N_W2FB + N_W3FB + N_F1TP + N_F2TP + N_W96FB + N_WOFB)

__global__ void prep_kernel(const float* __restrict__ w2, const float* __restrict__ w3,
                            const float* __restrict__ fw1, const float* __restrict__ fw2,
                            const float* __restrict__ wt, const float* __restrict__ wp,
                            const float* __restrict__ wg, const float* __restrict__ wo) {
    int i = blockIdx.x * blockDim.x + threadIdx.x;
    if (i < N_W2FB) {
        int lane = i & 31;
        int idx  = (i >> 5) & 7;
        int w    = (i >> 8) & 7;
        int tp   = i >> 11;                 // 0..4
        int g = lane >> 2, tg = lane & 3;
        int mt = idx >> 2, r = idx & 3;
        int o = mt * 16 + g + 8 * (r & 1);
        int tap = 2 * tp + (r >> 1);
        int c = w * 8 + 2 * tg;
        uint32_t v = 0;
        if (tap <= 8) {
            float lo = w2[o * 576 + c * 9 + tap];
            float hi = w2[o * 576 + (c + 1) * 9 + tap];
            v = pk(lo, hi);
        }
        g_w2fb[i] = v;
        return;
    }
    i -= N_W2FB;
    if (i < N_W3FB) {
        int lane = i & 31;
        int ridx = (i >> 5) & 1;
        int kc2  = (i >> 6) & 1;
        int t    = i >> 7;                  // 0..8
        int g = lane >> 2, tg = lane & 3;
        int o = g;                          // output channel 0..7
        int c = kc2 * 16 + 8 * ridx + 2 * tg;
        g_w3fb[i] = pk(w3[o * 288 + c * 9 + t], w3[o * 288 + (c + 1) * 9 + t]);
        return;
    }
    i -= N_W3FB;
    if (i < N_F1TP) {
        int kp = i / 64, jj = i % 64;
        g_fw1Tp[i] = pk(fw1[jj * 200 + 2 * kp], fw1[jj * 200 + 2 * kp + 1]);
        return;
    }
    i -= N_F1TP;
    if (i < N_F2TP) {
        int kp = i / 32, jj = i % 32;
        g_fw2Tp[i] = pk(fw2[jj * 64 + 2 * kp], fw2[jj * 64 + 2 * kp + 1]);
        return;
    }
    i -= N_F2TP;
    if (i < N_W96FB) {
        int lane = i & 31;
        int r    = (i >> 5) & 3;
        int kc   = (i >> 7) & 3;
        int wm   = i >> 9;                  // 0..5
        int g = lane >> 2, tg = lane & 3;
        int row = wm * 16 + g + 8 * (r & 1);    // 0..95
        int k0  = kc * 16 + 8 * (r >> 1) + 2 * tg;
        const float* src = (row < 32) ? wt : ((row < 64) ? wp : wg);
        g_w96fb[i] = pk(src[(row & 31) * 64 + k0], src[(row & 31) * 64 + k0 + 1]);
        return;
    }
    i -= N_W96FB;
    if (i < N_WOFB) {
        int lane = i & 31;
        int r    = (i >> 5) & 3;
        int kc2  = (i >> 7) & 1;
        int mt   = i >> 8;                  // 0..3
        int g = lane >> 2, tg = lane & 3;
        int row = mt * 16 + g + 8 * (r & 1);    // 0..63
        int k0  = kc2 * 16 + 8 * (r >> 1) + 2 * tg;
        g_wofb[i] = pk(wo[row * 32 + k0], wo[row * 32 + k0 + 1]);
    }
}

__global__ void __launch_bounds__(NTHREADS, 3) braggnn_kernel(
    const float* __restrict__ x,
    const float* __restrict__ w1, const float* __restrict__ b1,
    const float* __restrict__ bt, const float* __restrict__ bp,
    const float* __restrict__ bg, const float* __restrict__ bo,
    const float* __restrict__ b2, const float* __restrict__ b3,
    const float* __restrict__ fb1, const float* __restrict__ fb2,
    const float* __restrict__ fw3, const float* __restrict__ fb3,
    const float* __restrict__ fw4, const float* __restrict__ fb4,
    const float* __restrict__ fwo, const float* __restrict__ fbo,
    float* __restrict__ out)
{
    extern __shared__ float sm[];
    uint32_t* smu = (uint32_t*)sm;
    const int b    = blockIdx.x;
    const int tid  = threadIdx.x;
    const int w    = tid >> 5;
    const int lane = tid & 31;
    const int g    = lane >> 2;
    const int tg   = lane & 3;

    // ---- init: image, conv1 weights (packed), Gp pad rows ----
    for (int i = tid; i < 121; i += NTHREADS) sm[OFF_XS + i] = x[b * 121 + i];
    for (int i = tid; i < 512; i += NTHREADS) {        // W1Sp [64][12], 8 words used/row
        int o = i >> 3, ip = i & 7;
        float lo = (2 * ip <= 8) ? w1[o * 9 + 2 * ip] : 0.f;
        float hi = (2 * ip + 1 <= 8) ? w1[o * 9 + 2 * ip + 1] : 0.f;
        smu[OFF_W1S + o * 12 + ip] = pk(lo, hi);
    }
    for (int i = tid; i < 320; i += NTHREADS) smu[OFF_G + 40 * 40 + i] = 0u;  // Gp rows 40..47
    __syncthreads();

    // ---- im2col packed Pp [8 kp][88] ----
    for (int i = tid; i < 704; i += NTHREADS) {
        int kp = i / 88, s = i - kp * 88;
        float lo = 0.f, hi = 0.f;
        if (s < 81) {
            int t0 = 2 * kp, t1 = 2 * kp + 1;
            if (t0 <= 8) lo = sm[OFF_XS + (s / 9 + t0 / 3) * 11 + (s % 9) + t0 % 3];
            if (t1 <= 8) hi = sm[OFF_XS + (s / 9 + t1 / 3) * 11 + (s % 9) + t1 % 3];
        }
        smu[OFF_PP + kp * 88 + s] = pk(lo, hi);
    }
    __syncthreads();

    // ---- phase 1 (mma): A1[64][81] = W1[64][16] @ P[16][81], store packed pairs ----
    {
        const int m0 = (w >> 1) * 16;
        const int nbeg = (w & 1) ? 6 : 0, nend = (w & 1) ? 11 : 6;
        float D[6][4];
        #pragma unroll
        for (int j = 0; j < 6; j++) { D[j][0]=0.f; D[j][1]=0.f; D[j][2]=0.f; D[j][3]=0.f; }
        uint32_t a0 = smu[OFF_W1S + (m0 + g)     * 12 + tg];
        uint32_t a1 = smu[OFF_W1S + (m0 + g + 8) * 12 + tg];
        uint32_t a2 = smu[OFF_W1S + (m0 + g)     * 12 + tg + 4];
        uint32_t a3 = smu[OFF_W1S + (m0 + g + 8) * 12 + tg + 4];
        {
            int j = 0;
            for (int nt = nbeg; nt < nend; nt++, j++) {
                uint32_t b0 = smu[OFF_PP + tg       * 88 + nt * 8 + g];
                uint32_t b1 = smu[OFF_PP + (tg + 4) * 88 + nt * 8 + g];
                mma_bf16(D[j], a0, a1, a2, a3, b0, b1);
            }
        }
        const int c0 = m0 + g, c1 = m0 + g + 8;
        const float bia0 = b1[c0], bia1 = b1[c1];
        int j = 0;
        for (int nt = nbeg; nt < nend; nt++, j++)
            #pragma unroll
            for (int dd = 0; dd < 2; dd++) {
                int s = nt * 8 + 2 * tg + dd;
                float v0 = D[j][dd]     + bia0;
                float v1 = D[j][2 + dd] + bia1;
                float p0 = __shfl_xor_sync(0xffffffffu, v0, 4);
                float p1 = __shfl_xor_sync(0xffffffffu, v1, 4);
                if (!(g & 1) && s < 81) {
                    smu[OFF_A1 + (c0 >> 1) * 88 + s] = pk(v0, p0);
                    smu[OFF_A1 + (c1 >> 1) * 88 + s] = pk(v1, p1);
                }
            }
    }
    __syncthreads();

    // ---- phase 2 (mma): [theta|phi|g][96][81] = W96 @ A1 (M=16 per warp) ----
    if (w < 6) {
        float D[11][4];
        #pragma unroll
        for (int nt = 0; nt < 11; nt++) { D[nt][0]=0.f; D[nt][1]=0.f; D[nt][2]=0.f; D[nt][3]=0.f; }
        for (int kc = 0; kc < 4; kc++) {
            const uint32_t* af = &g_w96fb[(w * 4 + kc) * 128];
            uint32_t a0 = af[lane], a1 = af[32 + lane], a2 = af[64 + lane], a3 = af[96 + lane];
            #pragma unroll
            for (int nt = 0; nt < 11; nt++) {
                uint32_t b0 = smu[OFF_A1 + (kc * 8 + tg)     * 88 + nt * 8 + g];
                uint32_t b1 = smu[OFF_A1 + (kc * 8 + tg + 4) * 88 + nt * 8 + g];
                mma_bf16(D[nt], a0, a1, a2, a3, b0, b1);
            }
        }
        const int mat = w >> 1;                          // 0=theta 1=phi 2=g
        const float* bias = (mat == 0) ? bt : ((mat == 1) ? bp : bg);
        const int ch0 = (w & 1) * 16 + g, ch1 = ch0 + 8;
        const float bv0 = bias[ch0], bv1 = bias[ch1];
        if (mat == 2) {
            // Gp [tp][i]: t-pairs are local (dd)
            #pragma unroll
            for (int nt = 0; nt < 11; nt++) {
                int s0 = nt * 8 + 2 * tg;
                if (s0 < 81) {
                    float v00 = D[nt][0] + bv0, v01 = D[nt][1] + bv0;
                    float v10 = D[nt][2] + bv1, v11 = D[nt][3] + bv1;
                    float h0 = (s0 + 1 < 81) ? v01 : 0.f;
                    float h1 = (s0 + 1 < 81) ? v11 : 0.f;
                    smu[OFF_G + (nt * 4 + tg) * 40 + ch0] = pk(v00, h0);
                    smu[OFF_G + (nt * 4 + tg) * 40 + ch1] = pk(v10, h1);
                }
            }
        } else {
            // THp [s][ip] / PHp [ip][t]: i-pairs via g-parity shfl
            #pragma unroll
            for (int nt = 0; nt < 11; nt++)
                #pragma unroll
                for (int dd = 0; dd < 2; dd++) {
                    int s = nt * 8 + 2 * tg + dd;
                    float v0 = D[nt][dd]     + bv0;
                    float v1 = D[nt][2 + dd] + bv1;
                    float p0 = __shfl_xor_sync(0xffffffffu, v0, 4);
                    float p1 = __shfl_xor_sync(0xffffffffu, v1, 4);
                    if (!(g & 1) && s < 81) {
                        if (mat == 0) {
                            smu[OFF_TH + s * 20 + (ch0 >> 1)] = pk(v0, p0);
                            smu[OFF_TH + s * 20 + (ch1 >> 1)] = pk(v1, p1);
                        } else {
                            smu[OFF_PH + (ch0 >> 1) * 88 + s] = pk(v0, p0);
                            smu[OFF_PH + (ch1 >> 1) * 88 + s] = pk(v1, p1);
                        }
                    }
                }
        }
    }
    __syncthreads();

    // ---- phase 3a+3b fused: logits -> register softmax -> (local repack) -> Y ----
    if (w < 6) {
        const int m0 = w * 16;
        const int r0 = min(m0 + g, 80), r1 = min(m0 + g + 8, 80);
        float D[11][4];
        #pragma unroll
        for (int nt = 0; nt < 11; nt++) { D[nt][0]=0.f; D[nt][1]=0.f; D[nt][2]=0.f; D[nt][3]=0.f; }
        #pragma unroll
        for (int kc2 = 0; kc2 < 2; kc2++) {
            uint32_t a0 = smu[OFF_TH + r0 * 20 + kc2 * 8 + tg];
            uint32_t a1 = smu[OFF_TH + r1 * 20 + kc2 * 8 + tg];
            uint32_t a2 = smu[OFF_TH + r0 * 20 + kc2 * 8 + tg + 4];
            uint32_t a3 = smu[OFF_TH + r1 * 20 + kc2 * 8 + tg + 4];
            #pragma unroll
            for (int nt = 0; nt < 11; nt++) {
                uint32_t b0 = smu[OFF_PH + (kc2 * 8 + tg)     * 88 + nt * 8 + g];
                uint32_t b1 = smu[OFF_PH + (kc2 * 8 + tg + 4) * 88 + nt * 8 + g];
                mma_bf16(D[nt], a0, a1, a2, a3, b0, b1);
            }
        }
        // register softmax (rows m0+g, m0+g+8)
        float mx0 = -1e30f, mx1 = -1e30f;
        #pragma unroll
        for (int nt = 0; nt < 11; nt++)
            #pragma unroll
            for (int dd = 0; dd < 2; dd++) {
                int t = nt * 8 + 2 * tg + dd;
                if (t < 81) { mx0 = fmaxf(mx0, D[nt][dd]); mx1 = fmaxf(mx1, D[nt][2 + dd]); }
            }
        mx0 = fmaxf(mx0, __shfl_xor_sync(0xffffffffu, mx0, 1));
        mx0 = fmaxf(mx0, __shfl_xor_sync(0xffffffffu, mx0, 2));
        mx1 = fmaxf(mx1, __shfl_xor_sync(0xffffffffu, mx1, 1));
        mx1 = fmaxf(mx1, __shfl_xor_sync(0xffffffffu, mx1, 2));
        float s0 = 0.f, s1 = 0.f;
        #pragma unroll
        for (int nt = 0; nt < 11; nt++)
            #pragma unroll
            for (int dd = 0; dd < 2; dd++) {
                int t = nt * 8 + 2 * tg + dd;
                float e0 = (t < 81) ? __expf(D[nt][dd]     - mx0) : 0.f;
                float e1 = (t < 81) ? __expf(D[nt][2 + dd] - mx1) : 0.f;
                D[nt][dd] = e0; D[nt][2 + dd] = e1;
                s0 += e0; s1 += e1;
            }
        s0 += __shfl_xor_sync(0xffffffffu, s0, 1);
        s0 += __shfl_xor_sync(0xffffffffu, s0, 2);
        s1 += __shfl_xor_sync(0xffffffffu, s1, 1);
        s1 += __shfl_xor_sync(0xffffffffu, s1, 2);
        const float inv0 = 1.0f / s0, inv1 = 1.0f / s1;
        #pragma unroll
        for (int nt = 0; nt < 11; nt++)
            #pragma unroll
            for (int dd = 0; dd < 2; dd++) {
                D[nt][dd]     *= inv0;
                D[nt][2 + dd] *= inv1;
            }
        // 3b: Y = attn @ G; A-frags are register-local packs of D
        float Y[4][4];
        #pragma unroll
        for (int nt = 0; nt < 4; nt++) { Y[nt][0]=0.f; Y[nt][1]=0.f; Y[nt][2]=0.f; Y[nt][3]=0.f; }
        #pragma unroll
        for (int kc = 0; kc < 6; kc++) {
            uint32_t a0, a1, a2, a3;
            if (kc < 5) {
                a0 = pk(D[2 * kc][0],     D[2 * kc][1]);
                a1 = pk(D[2 * kc][2],     D[2 * kc][3]);
                a2 = pk(D[2 * kc + 1][0], D[2 * kc + 1][1]);
                a3 = pk(D[2 * kc + 1][2], D[2 * kc + 1][3]);
            } else {
                a0 = pk(D[10][0], D[10][1]);
                a1 = pk(D[10][2], D[10][3]);
                a2 = 0u; a3 = 0u;
            }
            #pragma unroll
            for (int nt = 0; nt < 4; nt++) {
                uint32_t b0 = smu[OFF_G + (kc * 8 + tg)     * 40 + nt * 8 + g];
                uint32_t b1 = smu[OFF_G + (kc * 8 + tg + 4) * 40 + nt * 8 + g];
                mma_bf16(Y[nt], a0, a1, a2, a3, b0, b1);
            }
        }
        const int sr0 = m0 + g, sr1 = m0 + g + 8;
        #pragma unroll
        for (int nt = 0; nt < 4; nt++) {
            if (sr0 < 81) smu[OFF_Y + (nt * 4 + tg) * 88 + sr0] = pk(Y[nt][0], Y[nt][1]);
            if (sr1 < 81) smu[OFF_Y + (nt * 4 + tg) * 88 + sr1] = pk(Y[nt][2], Y[nt][3]);
        }
    }
    __syncthreads();

    // ---- phase 3c (mma): Z[64][81] = wo @ Y^T + bo + residual, lrelu -> A1p ----
    {
        const int mt = w >> 1;
        const int nbeg = (w & 1) ? 6 : 0, nend = (w & 1) ? 11 : 6;
        float D[6][4];
        #pragma unroll
        for (int j = 0; j < 6; j++) { D[j][0]=0.f; D[j][1]=0.f; D[j][2]=0.f; D[j][3]=0.f; }
        #pragma unroll
        for (int kc2 = 0; kc2 < 2; kc2++) {
            const uint32_t* af = &g_wofb[(mt * 2 + kc2) * 128];
            uint32_t a0 = af[lane], a1 = af[32 + lane], a2 = af[64 + lane], a3 = af[96 + lane];
            int j = 0;
            for (int nt = nbeg; nt < nend; nt++, j++) {
                uint32_t b0 = smu[OFF_Y + (kc2 * 8 + tg)     * 88 + nt * 8 + g];
                uint32_t b1 = smu[OFF_Y + (kc2 * 8 + tg + 4) * 88 + nt * 8 + g];
                mma_bf16(D[j], a0, a1, a2, a3, b0, b1);
            }
        }
        const int c0 = mt * 16 + g, c1 = c0 + 8;
        const float bo0 = bo[c0], bo1 = bo[c1];
        int j = 0;
        for (int nt = nbeg; nt < nend; nt++, j++)
            #pragma unroll
            for (int dd = 0; dd < 2; dd++) {
                int s = nt * 8 + 2 * tg + dd;
                uint32_t w0 = smu[OFF_A1 + (c0 >> 1) * 88 + s];
                uint32_t w1v = smu[OFF_A1 + (c1 >> 1) * 88 + s];
                float r0v = (g & 1) ? bf_hi(w0)  : bf_lo(w0);
                float r1v = (g & 1) ? bf_hi(w1v) : bf_lo(w1v);
                float v0 = lrelu(D[j][dd]     + bo0 + r0v);
                float v1 = lrelu(D[j][2 + dd] + bo1 + r1v);
                float p0 = __shfl_xor_sync(0xffffffffu, v0, 4);
                float p1 = __shfl_xor_sync(0xffffffffu, v1, 4);
                if (!(g & 1) && s < 81) {
                    smu[OFF_A1 + (c0 >> 1) * 88 + s] = pk(v0, p0);
                    smu[OFF_A1 + (c1 >> 1) * 88 + s] = pk(v1, p1);
                }
            }
    }
    __syncthreads();

    // ---- phase 4 (mma): conv2 via tap-pair K=16 GEMMs, K-split by channel ----
    {
        const int c0p = w * 4;          // A1p row base (channel pairs)
        float* buf = &sm[OFF_RED + (w & 3) * 1824];
        #pragma unroll
        for (int pass = 0; pass < 2; pass++) {
            const int ntb = pass ? 4 : 0;
            const int ntn = pass ? 3 : 4;
            int rmv[4];
            #pragma unroll
            for (int q = 0; q < 4; q++) {
                int qq = (q < ntn) ? q : (ntn - 1);
                int p = (ntb + qq) * 8 + g;
                rmv[q] = (p < 49) ? (p / 7) * 9 + (p % 7) : 0;
            }
            float D[8][4];
            #pragma unroll
            for (int j = 0; j < 8; j++) { D[j][0]=0.f; D[j][1]=0.f; D[j][2]=0.f; D[j][3]=0.f; }
            for (int tp = 0; tp < 5; tp++) {
                int ta = 2 * tp, tb = (2 * tp + 1 <= 8) ? 2 * tp + 1 : 8;
                int off0 = (ta / 3) * 9 + ta % 3;
                int off1 = (tb / 3) * 9 + tb % 3;
                const uint32_t* af = &g_w2fb[(tp * 8 + w) * 256];
                uint32_t A[8];
                #pragma unroll
                for (int r = 0; r < 8; r++) A[r] = af[r * 32 + lane];
                for (int q = 0; q < ntn; q++) {
                    uint32_t b0 = smu[OFF_A1 + (c0p + tg) * 88 + rmv[q] + off0];
                    uint32_t b1 = smu[OFF_A1 + (c0p + tg) * 88 + rmv[q] + off1];
                    mma_bf16(D[q],     A[0], A[1], A[2], A[3], b0, b1);
                    mma_bf16(D[4 + q], A[4], A[5], A[6], A[7], b0, b1);
                }
            }
            if (w < 4) {
                for (int mt = 0; mt < 2; mt++)
                    for (int q = 0; q < ntn; q++)
                        #pragma unroll
                        for (int dd = 0; dd < 2; dd++) {
                            int o0 = mt * 16 + g, p = (ntb + q) * 8 + 2 * tg + dd;
                            buf[o0 * 57 + p]       = D[mt * 4 + q][dd];
                            buf[(o0 + 8) * 57 + p] = D[mt * 4 + q][2 + dd];
                        }
            }
            __syncthreads();
            if (w >= 4) {
                for (int mt = 0; mt < 2; mt++)
                    for (int q = 0; q < ntn; q++)
                        #pragma unroll
                        for (int dd = 0; dd < 2; dd++) {
                            int o0 = mt * 16 + g, p = (ntb + q) * 8 + 2 * tg + dd;
                            buf[o0 * 57 + p]       += D[mt * 4 + q][dd];
                            buf[(o0 + 8) * 57 + p] += D[mt * 4 + q][2 + dd];
                        }
            }
        }
        __syncthreads();
    }
    for (int e = tid; e < 784; e += NTHREADS) {     // reduce + bias + lrelu -> A3p packed
        int op = e / 49, p = e - op * 49;
        float s0 = b2[2 * op], s1 = b2[2 * op + 1];
        #pragma unroll
        for (int k = 0; k < 4; k++) {
            s0 += sm[OFF_RED + k * 1824 + (2 * op)     * 57 + p];
            s1 += sm[OFF_RED + k * 1824 + (2 * op + 1) * 57 + p];
        }
        smu[OFF_A3 + op * 56 + p] = pk(lrelu(s0), lrelu(s1));
    }
    __syncthreads();

    // ---- phase 5 (mma): conv3, taps split across warps ----
    {
        int rmv[4];
        #pragma unroll
        for (int nt = 0; nt < 4; nt++) {
            int n = nt * 8 + g;
            rmv[nt] = (n < 25) ? (n / 5) * 7 + (n % 5) : 0;
        }
        float D[4][4];
        #pragma unroll
        for (int nt = 0; nt < 4; nt++) { D[nt][0]=0.f; D[nt][1]=0.f; D[nt][2]=0.f; D[nt][3]=0.f; }
        for (int t = w; t < 9; t += 8) {
            const int off = (t / 3) * 7 + (t % 3);
            #pragma unroll
            for (int kc2 = 0; kc2 < 2; kc2++) {
                uint32_t a0 = g_w3fb[((t * 2 + kc2) * 2 + 0) * 32 + lane];
                uint32_t a2 = g_w3fb[((t * 2 + kc2) * 2 + 1) * 32 + lane];
                #pragma unroll
                for (int nt = 0; nt < 4; nt++) {
                    uint32_t b0 = smu[OFF_A3 + (kc2 * 8 + tg)     * 56 + rmv[nt] + off];
                    uint32_t b1 = smu[OFF_A3 + (kc2 * 8 + tg + 4) * 56 + rmv[nt] + off];
                    mma_bf16(D[nt], a0, 0u, a2, 0u, b0, b1);
                }
            }
        }
        float* buf3 = &sm[OFF_RED3 + w * 264];
        #pragma unroll
        for (int nt = 0; nt < 4; nt++)
            #pragma unroll
            for (int dd = 0; dd < 2; dd++)
                buf3[g * 33 + nt * 8 + 2 * tg + dd] = D[nt][dd];
    }
    __syncthreads();
    if (tid < 100) {     // reduce 8 tap-partials + bias + lrelu -> flat packed
        int f0 = 2 * tid, f1 = f0 + 1;
        int o0 = f0 / 25, p0 = f0 % 25;
        int o1 = f1 / 25, p1 = f1 % 25;
        float sA = b3[o0], sB = b3[o1];
        #pragma unroll
        for (int ww = 0; ww < 8; ww++) {
            sA += sm[OFF_RED3 + ww * 264 + o0 * 33 + p0];
            sB += sm[OFF_RED3 + ww * 264 + o1 * 33 + p1];
        }
        smu[OFF_FLAT + tid] = pk(lrelu(sA), lrelu(sB));
    }
    __syncthreads();

    // ---- phase 6: MLP (fc1/fc2 bf16-packed, rest fp32) ----
    float* scr  = &sm[OFF_FCS];
    float* sc2  = &sm[OFF_FC2S];
    float* f2 = &sm[OFF_F2];
    float* f3 = &sm[OFF_F3];
    float* f4 = &sm[OFF_F4];

    {   // fc1: 200 -> 64, packed k-pairs
        int q = tid >> 6, j = tid & 63;
        float acc = 0.f;
        int k0 = q * 25;
        for (int kp = 0; kp < 25; kp++) {
            uint32_t wv = g_fw1Tp[(k0 + kp) * 64 + j];
            uint32_t xv = smu[OFF_FLAT + k0 + kp];
            acc += bf_lo(wv) * bf_lo(xv) + bf_hi(wv) * bf_hi(xv);
        }
        scr[q * 64 + j] = acc;
    }
    __syncthreads();
    if (tid < 32) {     // reduce + lrelu + pack f1
        int j0 = 2 * tid, j1 = j0 + 1;
        float a0 = scr[j0] + scr[64 + j0] + scr[128 + j0] + scr[192 + j0] + fb1[j0];
        float a1 = scr[j1] + scr[64 + j1] + scr[128 + j1] + scr[192 + j1] + fb1[j1];
        smu[OFF_F1 + tid] = pk(lrelu(a0), lrelu(a1));
    }
    __syncthreads();
    if (tid < 128) {    // fc2: 64 -> 32, packed k-pairs
        int q = tid >> 5, j = tid & 31;
        float acc = 0.f;
        int k0 = q * 8;
        for (int kp = 0; kp < 8; kp++) {
            uint32_t wv = g_fw2Tp[(k0 + kp) * 32 + j];
            uint32_t xv = smu[OFF_F1 + k0 + kp];
            acc += bf_lo(wv) * bf_lo(xv) + bf_hi(wv) * bf_hi(xv);
        }
        sc2[q * 32 + j] = acc;
    }
    __syncthreads();
    if (tid < 32)
        f2[tid] = lrelu(sc2[tid] + sc2[32 + tid] + sc2[64 + tid] + sc2[96 + tid] + fb2[tid]);
    __syncthreads();
    if (tid < 64) {     // fc3: 32 -> 16
        int j = tid >> 2, q = tid & 3;
        float acc = 0.f;
        const float* wr = &fw3[j * 32 + q * 8];
        for (int k = 0; k < 8; k++) acc += wr[k] * f2[q * 8 + k];
        acc += __shfl_xor_sync(0xffffffffu, acc, 1);
        acc += __shfl_xor_sync(0xffffffffu, acc, 2);
        if (q == 0) f3[j] = lrelu(acc + fb3[j]);
    }
    __syncthreads();
    if (tid < 32) {     // fc4: 16 -> 8
        int j = tid >> 2, q = tid & 3;
        float acc = 0.f;
        const float* wr = &fw4[j * 16 + q * 4];
        for (int k = 0; k < 4; k++) acc += wr[k] * f3[q * 4 + k];
        acc += __shfl_xor_sync(0xffffffffu, acc, 1);
        acc += __shfl_xor_sync(0xffffffffu, acc, 2);
        if (q == 0) f4[j] = lrelu(acc + fb4[j]);
    }
    __syncthreads();
    if (tid < 2) {      // fco: 8 -> 2
        float acc = fbo[tid];
        const float* wr = &fwo[tid * 8];
        #pragma unroll
        for (int k = 0; k < 8; k++) acc += wr[k] * f4[k];
        out[b * 2 + tid] = acc;
    }
}

extern "C" void kernel_launch(void* const* d_in, const int* in_sizes, int n_in,
                              void* d_out, int out_size) {
    const float* x   = (const float*)d_in[0];
    const float* w1  = (const float*)d_in[1];
    const float* b1  = (const float*)d_in[2];
    const float* wt  = (const float*)d_in[3];
    const float* bt  = (const float*)d_in[4];
    const float* wp  = (const float*)d_in[5];
    const float* bp  = (const float*)d_in[6];
    const float* wg  = (const float*)d_in[7];
    const float* bg  = (const float*)d_in[8];
    const float* wo  = (const float*)d_in[9];
    const float* bo  = (const float*)d_in[10];
    const float* w2  = (const float*)d_in[11];
    const float* b2  = (const float*)d_in[12];
    const float* w3  = (const float*)d_in[13];
    const float* b3  = (const float*)d_in[14];
    const float* fw1 = (const float*)d_in[15];
    const float* fb1 = (const float*)d_in[16];
    const float* fw2 = (const float*)d_in[17];
    const float* fb2 = (const float*)d_in[18];
    const float* fw3 = (const float*)d_in[19];
    const float* fb3 = (const float*)d_in[20];
    const float* fw4 = (const float*)d_in[21];
    const float* fb4 = (const float*)d_in[22];
    const float* fwo = (const float*)d_in[23];
    const float* fbo = (const float*)d_in[24];
    float* out = (float*)d_out;

    int B = in_sizes[0] / 121;

    prep_kernel<<<(PREP_TOTAL + 255) / 256, 256>>>(w2, w3, fw1, fw2, wt, wp, wg, wo);

    cudaFuncSetAttribute(braggnn_kernel,
                         cudaFuncAttributeMaxDynamicSharedMemorySize, SMEM_BYTES);
    braggnn_kernel<<<B, NTHREADS, SMEM_BYTES>>>(
        x, w1, b1, bt, bp, bg, bo, b2, b3,
        fb1, fb2, fw3, fb3, fw4, fb4, fwo, fbo, out);
}